// round 12
// baseline (speedup 1.0000x reference)
#include <cuda_runtime.h>
#include <cuda_bf16.h>
#include <cuda_fp16.h>
#include <math.h>
#include <float.h>
#include <stdint.h>

#define Nn   50000
#define FIN  64
#define Hh   256
#define Ee   800000
#define Gg   2048
#define Ll   4
#define Tt   4
#define EPSc 1e-5f

#define MTILES ((Nn + 127) / 128)   // 391
#define Mpad   (MTILES * 128)       // 50048
#define EPAD   (Ee + 4 * Nn)        // padded CSR capacity

// ---------------- scratch ----------------
__device__ __align__(16) float  g_h  [Nn * Hh];
__device__ __align__(16) __half g_hWh[(size_t)Mpad * Hh];   // fp16 message rows
__device__ float g_isd[Nn];
__device__ int   g_cnt[Nn];
__device__ int   g_off[Nn + 1];
__device__ int   g_cur[Nn];
__device__ __align__(16) int   g_csr[EPAD];
__device__ __align__(16) float g_wgt[EPAD];
__device__ int   g_part[64];
__device__ __align__(16) float g_pool[Gg * 2 * Hh];
__device__ __align__(16) float g_f1[Gg * Hh];
__device__ __align__(16) float g_f2[Gg * (Hh / 2)];
__device__ __align__(16) __nv_bfloat16 g_Ahi[(size_t)Mpad * Hh];
__device__ __align__(16) __nv_bfloat16 g_Alo[(size_t)Mpad * Hh];
__device__ __align__(16) __nv_bfloat16 g_Bhi[Ll * Hh * Hh];
__device__ __align__(16) __nv_bfloat16 g_Blo[Ll * Hh * Hh];
__device__ __align__(16) __nv_bfloat16 g_Xhi[(size_t)Mpad * FIN];
__device__ __align__(16) __nv_bfloat16 g_Xlo[(size_t)Mpad * FIN];
__device__ __align__(16) __nv_bfloat16 g_PBhi[FIN * Hh];
__device__ __align__(16) __nv_bfloat16 g_PBlo[FIN * Hh];

// ---------------- asm helpers ----------------
__device__ __forceinline__ uint32_t smem_u32(const void* p) {
    uint32_t a;
    asm("{ .reg .u64 t; cvta.to.shared.u64 t, %1; cvt.u32.u64 %0, t; }" : "=r"(a) : "l"(p));
    return a;
}
#define CPA(dst, src) \
    asm volatile("cp.async.cg.shared.global [%0], [%1], 16;" :: "r"(dst), "l"(src) : "memory")
#define LDSM4(r, addr) \
    asm volatile("ldmatrix.sync.aligned.m8n8.x4.shared.b16 {%0,%1,%2,%3}, [%4];" \
        : "=r"((r)[0]), "=r"((r)[1]), "=r"((r)[2]), "=r"((r)[3]) : "r"(addr))
#define LDSM4T(r, addr) \
    asm volatile("ldmatrix.sync.aligned.m8n8.x4.trans.shared.b16 {%0,%1,%2,%3}, [%4];" \
        : "=r"((r)[0]), "=r"((r)[1]), "=r"((r)[2]), "=r"((r)[3]) : "r"(addr))
#define MMA16816(c, a, b) \
    asm volatile("mma.sync.aligned.m16n8k16.row.col.f32.bf16.bf16.f32 " \
        "{%0,%1,%2,%3}, {%4,%5,%6,%7}, {%8,%9}, {%0,%1,%2,%3};" \
        : "+f"((c)[0]), "+f"((c)[1]), "+f"((c)[2]), "+f"((c)[3]) \
        : "r"((a)[0]), "r"((a)[1]), "r"((a)[2]), "r"((a)[3]), "r"((b)[0]), "r"((b)[1]))

__device__ __forceinline__ uint32_t pack_hi2(float x, float y) {
    __nv_bfloat16 a = __float2bfloat16(x), b = __float2bfloat16(y);
    return ((uint32_t)*(uint16_t*)&b << 16) | *(uint16_t*)&a;
}
__device__ __forceinline__ uint32_t pack_lo2(float x, float y) {
    __nv_bfloat16 a = __float2bfloat16(x), b = __float2bfloat16(y);
    __nv_bfloat16 la = __float2bfloat16(x - __bfloat162float(a));
    __nv_bfloat16 lb = __float2bfloat16(y - __bfloat162float(b));
    return ((uint32_t)*(uint16_t*)&lb << 16) | *(uint16_t*)&la;
}
// 4 fp16 (uint2) -> 4 fp32 fma into acc
__device__ __forceinline__ void fma4(float4& acc, uint2 q, float w) {
    float2 a = __half22float2(*(__half2*)&q.x);
    float2 b = __half22float2(*(__half2*)&q.y);
    acc.x = fmaf(a.x, w, acc.x);
    acc.y = fmaf(a.y, w, acc.y);
    acc.z = fmaf(b.x, w, acc.z);
    acc.w = fmaf(b.y, w, acc.w);
}

// ---------------- setup kernels ----------------
__global__ void k_zero_cnt() {
    int i = blockIdx.x * blockDim.x + threadIdx.x;
    if (i < Nn) g_cnt[i] = 0;
}
__global__ void k_split_x(const float* __restrict__ x) {
    int idx = blockIdx.x * blockDim.x + threadIdx.x;
    if (idx >= Nn * FIN / 4) return;
    float4 v = *(const float4*)&x[idx * 4];
    uint2 hv, lv;
    hv.x = pack_hi2(v.x, v.y); hv.y = pack_hi2(v.z, v.w);
    lv.x = pack_lo2(v.x, v.y); lv.y = pack_lo2(v.z, v.w);
    *(uint2*)&g_Xhi[idx * 4] = hv;
    *(uint2*)&g_Xlo[idx * 4] = lv;
}
__global__ void k_wsplit(const float* __restrict__ convW, const float* __restrict__ projW) {
    int idx = blockIdx.x * blockDim.x + threadIdx.x;
    if (idx < Ll * Hh * Hh) {
        float w = convW[idx];
        __nv_bfloat16 hi = __float2bfloat16(w);
        g_Bhi[idx] = hi;
        g_Blo[idx] = __float2bfloat16(w - __bfloat162float(hi));
    } else if (idx < Ll * Hh * Hh + FIN * Hh) {
        int j = idx - Ll * Hh * Hh;
        float w = projW[j];
        __nv_bfloat16 hi = __float2bfloat16(w);
        g_PBhi[j] = hi;
        g_PBlo[j] = __float2bfloat16(w - __bfloat162float(hi));
    }
}
__global__ void k_count_edges(const int* __restrict__ ei) {
    int e = blockIdx.x * blockDim.x + threadIdx.x;
    if (e < Ee) atomicAdd(&g_cnt[ei[Ee + e]], 1);
}
// scan over PADDED counts: (cnt+3)&~3  -> every off[v] multiple of 4
__global__ void k_scan_block() {
    __shared__ int s[1024];
    int gid = blockIdx.x * 1024 + threadIdx.x;
    int v = (gid < Nn) ? ((g_cnt[gid] + 3) & ~3) : 0;
    s[threadIdx.x] = v;
    for (int d = 1; d < 1024; d <<= 1) {
        __syncthreads();
        int t = (threadIdx.x >= d) ? s[threadIdx.x - d] : 0;
        __syncthreads();
        s[threadIdx.x] += t;
    }
    __syncthreads();
    if (gid < Nn) g_off[gid] = s[threadIdx.x] - v;
    if (threadIdx.x == 1023) g_part[blockIdx.x] = s[1023];
}
__global__ void k_scan_add() {
    __shared__ int base;
    if (threadIdx.x == 0) {
        int acc = 0;
        for (int i = 0; i < blockIdx.x; i++) acc += g_part[i];
        base = acc;
    }
    __syncthreads();
    int gid = blockIdx.x * 1024 + threadIdx.x;
    if (gid < Nn) {
        int v = g_off[gid] + base;
        g_off[gid] = v;
        g_cur[gid] = v;
        g_isd[gid] = rsqrtf(1.0f + (float)g_cnt[gid]);
        if (gid == Nn - 1) g_off[Nn] = v + ((g_cnt[gid] + 3) & ~3);
    }
}
__global__ void k_csr_fill(const int* __restrict__ ei) {
    int e = blockIdx.x * blockDim.x + threadIdx.x;
    if (e < Ee) {
        int s = ei[e];
        int d = ei[Ee + e];
        int p = atomicAdd(&g_cur[d], 1);
        g_csr[p] = s;
        g_wgt[p] = g_isd[s] * g_isd[d];
    }
}
// fill pad tail [off[v]+cnt[v], off[v+1]) with {src=v, w=0}  (no-op edges)
__global__ void k_pad() {
    int v = blockIdx.x * blockDim.x + threadIdx.x;
    if (v >= Nn) return;
    int p = g_off[v] + g_cnt[v], e = g_off[v + 1];
    for (; p < e; p++) { g_csr[p] = v; g_wgt[p] = 0.f; }
}

// ---------------- bf16x3 mma.sync GEMM, 4-slot K16 cp.async ring ----------------
// MODE 0 (conv): A = g_Ahi/g_Alo [Mpad,256], B = g_Bhi/g_Blo + layer, C = g_hWh (fp16)
// MODE 1 (proj): A = g_Xhi/g_Xlo [Mpad,64],  B = g_PBhi/g_PBlo, C = relu(.+bias) -> g_h + split
#define SLOT   20992
#define ALO_O  6144
#define BHI_O  12288
#define BLO_O  16640
#define SMEM_G (4 * SLOT)   // 83968

template<int KSTAGES, int MODE>
__global__ __launch_bounds__(256, 2) void k_gemm_mma(int layer, const float* __restrict__ bias) {
    extern __shared__ __align__(16) unsigned char smraw[];
    const int tid = threadIdx.x, lane = tid & 31, wid = tid >> 5;
    const int warp_m = wid & 3, warp_n = wid >> 2;
    const int m0 = blockIdx.x * 128, n0 = blockIdx.y * 128;
    const uint32_t sb = smem_u32(smraw);
    const int kdim = KSTAGES * 16;

    const __nv_bfloat16* Ah = (MODE == 0) ? g_Ahi : g_Xhi;
    const __nv_bfloat16* Al = (MODE == 0) ? g_Alo : g_Xlo;
    const __nv_bfloat16* Bh = (MODE == 0) ? g_Bhi + (size_t)layer * Hh * Hh : g_PBhi;
    const __nv_bfloat16* Bl = (MODE == 0) ? g_Blo + (size_t)layer * Hh * Hh : g_PBlo;

    const int a_r = tid >> 1, a_c = tid & 1;
    const int b_r = tid >> 4, b_c = tid & 15;

#define LOAD_STAGE(slotbase, kt) do { \
        int k0 = (kt) * 16; \
        CPA((slotbase) + a_r * 48 + a_c * 16, \
            Ah + (size_t)(m0 + a_r) * kdim + k0 + a_c * 8); \
        CPA((slotbase) + ALO_O + a_r * 48 + a_c * 16, \
            Al + (size_t)(m0 + a_r) * kdim + k0 + a_c * 8); \
        CPA((slotbase) + BHI_O + b_r * 272 + b_c * 16, \
            Bh + (size_t)(k0 + b_r) * Hh + n0 + b_c * 8); \
        CPA((slotbase) + BLO_O + b_r * 272 + b_c * 16, \
            Bl + (size_t)(k0 + b_r) * Hh + n0 + b_c * 8); \
        asm volatile("cp.async.commit_group;" ::: "memory"); \
    } while (0)

    float acc[2][8][4];
    #pragma unroll
    for (int i = 0; i < 2; i++)
        #pragma unroll
        for (int j = 0; j < 8; j++)
            #pragma unroll
            for (int q = 0; q < 4; q++) acc[i][j][q] = 0.f;

    const uint32_t aoff = sb + (warp_m * 32 + (lane & 15)) * 48 + (lane >> 4) * 16;
    const uint32_t boff = sb + BHI_O + (lane & 15) * 272 + (warp_n * 8 + (lane >> 4)) * 16;

    LOAD_STAGE(sb, 0);
    LOAD_STAGE(sb + SLOT, 1);
    LOAD_STAGE(sb + 2 * SLOT, 2);

    #pragma unroll
    for (int kt = 0; kt < KSTAGES; kt++) {
        const uint32_t s = (kt & 3) * SLOT;
        asm volatile("cp.async.wait_group 2;" ::: "memory");
        __syncthreads();
        if (kt + 3 < KSTAGES) {
            LOAD_STAGE(sb + ((kt + 3) & 3) * SLOT, kt + 3);
        } else {
            asm volatile("cp.async.commit_group;" ::: "memory");
        }

        uint32_t ah[2][4], al[2][4], bh[4][4], bl[4][4];
        #pragma unroll
        for (int mt = 0; mt < 2; mt++) {
            LDSM4(ah[mt], aoff + s + mt * 768);
            LDSM4(al[mt], aoff + s + ALO_O + mt * 768);
        }
        #pragma unroll
        for (int nt = 0; nt < 4; nt++) {
            LDSM4T(bh[nt], boff + s + nt * 32);
            LDSM4T(bl[nt], boff + s + (BLO_O - BHI_O) + nt * 32);
        }
        #pragma unroll
        for (int mt = 0; mt < 2; mt++)
            #pragma unroll
            for (int nt = 0; nt < 4; nt++)
                #pragma unroll
                for (int nb = 0; nb < 2; nb++) {
                    float* c = acc[mt][nt * 2 + nb];
                    MMA16816(c, ah[mt], &bh[nt][nb * 2]);
                    MMA16816(c, ah[mt], &bl[nt][nb * 2]);
                    MMA16816(c, al[mt], &bh[nt][nb * 2]);
                }
    }
#undef LOAD_STAGE

    #pragma unroll
    for (int mt = 0; mt < 2; mt++) {
        int rbase = m0 + warp_m * 32 + mt * 16 + (lane >> 2);
        #pragma unroll
        for (int half = 0; half < 2; half++) {
            int r = rbase + half * 8;
            #pragma unroll
            for (int j = 0; j < 8; j++) {
                int n = n0 + warp_n * 64 + j * 8 + (lane & 3) * 2;
                float vx = acc[mt][j][half * 2 + 0];
                float vy = acc[mt][j][half * 2 + 1];
                if (MODE == 0) {
                    __half2 hv = __floats2half2_rn(vx, vy);
                    *(__half2*)&g_hWh[(size_t)r * Hh + n] = hv;
                } else if (r < Nn) {
                    float2 bi = *(const float2*)&bias[n];
                    vx = fmaxf(vx + bi.x, 0.f);
                    vy = fmaxf(vy + bi.y, 0.f);
                    float2 v = {vx, vy};
                    *(float2*)&g_h[(size_t)r * Hh + n] = v;
                    *(uint32_t*)&g_Ahi[(size_t)r * Hh + n] = pack_hi2(vx, vy);
                    *(uint32_t*)&g_Alo[(size_t)r * Hh + n] = pack_lo2(vx, vy);
                }
            }
        }
    }
}

// ---------------- SIMT SGEMM (head only) ----------------
__global__ void k_sgemm(const float* __restrict__ B, const float* __restrict__ bias,
                        int M, int N, int K, int sel) {
    const float* A = (sel == 2) ? g_pool : g_f1;
    float*       C = (sel == 2) ? g_f1  : g_f2;

    __shared__ float As[16][64];
    __shared__ float Bs[16][68];

    int tid = threadIdx.x;
    int m0 = blockIdx.y * 64, n0 = blockIdx.x * 64;
    int tr = tid >> 4, tc = tid & 15;
    int arow = tid >> 2, aq = (tid & 3) * 4;
    int brow = tid >> 4, bq = (tid & 15) * 4;

    float acc[4][4];
    #pragma unroll
    for (int i = 0; i < 4; i++)
        #pragma unroll
        for (int j = 0; j < 4; j++) acc[i][j] = 0.f;

    for (int k0 = 0; k0 < K; k0 += 16) {
        float4 av;
        if (m0 + arow < M)
            av = *reinterpret_cast<const float4*>(&A[(size_t)(m0 + arow) * K + k0 + aq]);
        else
            av = make_float4(0.f, 0.f, 0.f, 0.f);
        As[aq + 0][arow] = av.x;
        As[aq + 1][arow] = av.y;
        As[aq + 2][arow] = av.z;
        As[aq + 3][arow] = av.w;

        float4 bv = *reinterpret_cast<const float4*>(&B[(size_t)(k0 + brow) * N + n0 + bq]);
        Bs[brow][bq + 0] = bv.x;
        Bs[brow][bq + 1] = bv.y;
        Bs[brow][bq + 2] = bv.z;
        Bs[brow][bq + 3] = bv.w;
        __syncthreads();

        #pragma unroll
        for (int k = 0; k < 16; k++) {
            float arr[4], br[4];
            #pragma unroll
            for (int i = 0; i < 4; i++) arr[i] = As[k][tr * 4 + i];
            #pragma unroll
            for (int j = 0; j < 4; j++) br[j] = Bs[k][tc * 4 + j];
            #pragma unroll
            for (int i = 0; i < 4; i++)
                #pragma unroll
                for (int j = 0; j < 4; j++) acc[i][j] = fmaf(arr[i], br[j], acc[i][j]);
        }
        __syncthreads();
    }

    #pragma unroll
    for (int i = 0; i < 4; i++) {
        int m = m0 + tr * 4 + i;
        if (m >= M) continue;
        #pragma unroll
        for (int j = 0; j < 4; j++) {
            int n = n0 + tc * 4 + j;
            float v = fmaxf(acc[i][j] + bias[n], 0.f);
            C[(size_t)m * N + n] = v;
        }
    }
}

// ---------------- fused aggregation: 2 warps/node, aligned int4/float4 meta ----------------
__global__ __launch_bounds__(256) void k_agg_fused(
        const float* __restrict__ bias, const float* __restrict__ gamma,
        const float* __restrict__ beta, const float* __restrict__ mean,
        const float* __restrict__ var) {
    int v = blockIdx.x * 4 + (threadIdx.x >> 6);
    if (v >= Nn) return;
    int c = (threadIdx.x & 63) * 4;   // 4 features per thread

    float idv = g_isd[v];
    float ws = idv * idv;

    float4 acc;
    {
        uint2 sr = *(const uint2*)&g_hWh[(size_t)v * Hh + c];
        float2 s0 = __half22float2(*(__half2*)&sr.x);
        float2 s1 = __half22float2(*(__half2*)&sr.y);
        acc = make_float4(s0.x * ws, s0.y * ws, s1.x * ws, s1.y * ws);
    }

    int j = g_off[v], e = g_off[v + 1];   // both multiples of 4
    for (; j < e; j += 4) {
        int4   s4 = *(const int4*)&g_csr[j];
        float4 w4 = *(const float4*)&g_wgt[j];
        uint2 q0 = *(const uint2*)&g_hWh[(size_t)s4.x * Hh + c];
        uint2 q1 = *(const uint2*)&g_hWh[(size_t)s4.y * Hh + c];
        uint2 q2 = *(const uint2*)&g_hWh[(size_t)s4.z * Hh + c];
        uint2 q3 = *(const uint2*)&g_hWh[(size_t)s4.w * Hh + c];
        fma4(acc, q0, w4.x);
        fma4(acc, q1, w4.y);
        fma4(acc, q2, w4.z);
        fma4(acc, q3, w4.w);
    }

    float4 bi = *(const float4*)&bias[c];
    float4 ga = *(const float4*)&gamma[c];
    float4 be = *(const float4*)&beta[c];
    float4 me = *(const float4*)&mean[c];
    float4 va = *(const float4*)&var[c];
    float4 res = *(const float4*)&g_h[(size_t)v * Hh + c];

    float4 o;
    o.x = fmaxf((acc.x + bi.x - me.x) * (ga.x * rsqrtf(va.x + EPSc)) + be.x, 0.f) + res.x;
    o.y = fmaxf((acc.y + bi.y - me.y) * (ga.y * rsqrtf(va.y + EPSc)) + be.y, 0.f) + res.y;
    o.z = fmaxf((acc.z + bi.z - me.z) * (ga.z * rsqrtf(va.z + EPSc)) + be.z, 0.f) + res.z;
    o.w = fmaxf((acc.w + bi.w - me.w) * (ga.w * rsqrtf(va.w + EPSc)) + be.w, 0.f) + res.w;
    *(float4*)&g_h[(size_t)v * Hh + c] = o;

    uint2 hv, lv;
    hv.x = pack_hi2(o.x, o.y); hv.y = pack_hi2(o.z, o.w);
    lv.x = pack_lo2(o.x, o.y); lv.y = pack_lo2(o.z, o.w);
    *(uint2*)&g_Ahi[(size_t)v * Hh + c] = hv;
    *(uint2*)&g_Alo[(size_t)v * Hh + c] = lv;
}

// ---------------- pooling ----------------
__global__ void k_pool(const int* __restrict__ batch) {
    __shared__ int sbb[2];
    int grp = blockIdx.x, t = threadIdx.x;
    if (t < 2) {
        int key = grp + t;
        int lo = 0, hi = Nn;
        while (lo < hi) {
            int mid = (lo + hi) >> 1;
            if (batch[mid] < key) lo = mid + 1; else hi = mid;
        }
        sbb[t] = lo;
    }
    __syncthreads();
    int s = sbb[0], e = sbb[1];
    float sum = 0.f, mx = -FLT_MAX;
    for (int i = s; i < e; i++) {
        float v = g_h[(size_t)i * Hh + t];
        sum += v;
        mx = fmaxf(mx, v);
    }
    float c = (float)(e - s);
    g_pool[(size_t)grp * (2 * Hh) + t]      = sum / fmaxf(c, 1.f);
    g_pool[(size_t)grp * (2 * Hh) + Hh + t] = mx;
}

// ---------------- final tiny GEMM ----------------
__global__ void k_head3(const float* __restrict__ W, const float* __restrict__ b,
                        float* __restrict__ out) {
    int idx = blockIdx.x * blockDim.x + threadIdx.x;
    if (idx >= Gg * Tt) return;
    int r = idx >> 2, c = idx & 3;
    float acc = b[c];
    const float* row = &g_f2[(size_t)r * 128];
    #pragma unroll 8
    for (int k = 0; k < 128; k++) acc = fmaf(row[k], W[k * 4 + c], acc);
    out[idx] = acc;
}

// ---------------- launch ----------------
extern "C" void kernel_launch(void* const* d_in, const int* in_sizes, int n_in,
                              void* d_out, int out_size) {
    const float* x     = (const float*)d_in[0];
    const int*   ei    = (const int*)d_in[1];
    const int*   batch = (const int*)d_in[2];
    const float* projW = (const float*)d_in[3];
    const float* projb = (const float*)d_in[4];
    const float* convW = (const float*)d_in[5];
    const float* convb = (const float*)d_in[6];
    const float* gamma = (const float*)d_in[7];
    const float* beta  = (const float*)d_in[8];
    const float* mean  = (const float*)d_in[9];
    const float* var   = (const float*)d_in[10];
    const float* W1 = (const float*)d_in[11];
    const float* b1 = (const float*)d_in[12];
    const float* W2 = (const float*)d_in[13];
    const float* b2 = (const float*)d_in[14];
    const float* W3 = (const float*)d_in[15];
    const float* b3 = (const float*)d_in[16];
    float* out = (float*)d_out;

    const int SCAN_B = (Nn + 1023) / 1024;

    cudaFuncSetAttribute(k_gemm_mma<16, 0>, cudaFuncAttributeMaxDynamicSharedMemorySize, SMEM_G);
    cudaFuncSetAttribute(k_gemm_mma<4, 1>, cudaFuncAttributeMaxDynamicSharedMemorySize, SMEM_G);

    k_zero_cnt <<<(Nn + 255) / 256, 256>>>();
    k_split_x  <<<(Nn * FIN / 4 + 255) / 256, 256>>>(x);
    k_wsplit   <<<(Ll * Hh * Hh + FIN * Hh + 255) / 256, 256>>>(convW, projW);

    // projection via mma path
    k_gemm_mma<4, 1><<<dim3(MTILES, 2), 256, SMEM_G>>>(0, projb);

    // padded CSR build
    k_count_edges<<<(Ee + 255) / 256, 256>>>(ei);
    k_scan_block <<<SCAN_B, 1024>>>();
    k_scan_add   <<<SCAN_B, 1024>>>();
    k_csr_fill   <<<(Ee + 255) / 256, 256>>>(ei);
    k_pad        <<<(Nn + 255) / 256, 256>>>();

    // 4 GCN layers
    for (int l = 0; l < Ll; l++) {
        k_gemm_mma<16, 0><<<dim3(MTILES, 2), 256, SMEM_G>>>(l, nullptr);
        k_agg_fused<<<(Nn + 3) / 4, 256>>>(convb + l * Hh, gamma + l * Hh, beta + l * Hh,
                                           mean + l * Hh, var + l * Hh);
    }

    // pooling + head
    k_pool<<<Gg, 256>>>(batch);
    k_sgemm<<<dim3(Hh / 64, Gg / 64), 256>>>(W1, b1, Gg, Hh, 2 * Hh, 2);
    k_sgemm<<<dim3((Hh / 2) / 64, Gg / 64), 256>>>(W2, b2, Gg, Hh / 2, Hh, 3);
    k_head3<<<(Gg * Tt + 255) / 256, 256>>>(W3, b3, out);
}

// round 13
// speedup vs baseline: 1.1106x; 1.1106x over previous
#include <cuda_runtime.h>
#include <cuda_bf16.h>
#include <cuda_fp16.h>
#include <math.h>
#include <float.h>
#include <stdint.h>

#define Nn   50000
#define FIN  64
#define Hh   256
#define Ee   800000
#define Gg   2048
#define Ll   4
#define Tt   4
#define EPSc 1e-5f

#define MTILES ((Nn + 127) / 128)   // 391
#define Mpad   (MTILES * 128)       // 50048

// ---------------- scratch ----------------
// h is stored ONLY as the bf16 hi/lo pair (g_Ahi + g_Alo); no fp32 copy.
__device__ __align__(16) __half g_hWh[(size_t)Mpad * Hh];   // fp16 message rows
__device__ float g_isd[Nn];
__device__ int   g_cnt[Nn];
__device__ int   g_off[Nn + 1];
__device__ int   g_cur[Nn];
__device__ int   g_csr[Ee];
__device__ float g_wgt[Ee];
__device__ int   g_part[64];
__device__ __align__(16) float g_pool[Gg * 2 * Hh];
__device__ __align__(16) float g_f1[Gg * Hh];
__device__ __align__(16) float g_f2[Gg * (Hh / 2)];
__device__ __align__(16) __nv_bfloat16 g_Ahi[(size_t)Mpad * Hh];
__device__ __align__(16) __nv_bfloat16 g_Alo[(size_t)Mpad * Hh];
__device__ __align__(16) __nv_bfloat16 g_Bhi[Ll * Hh * Hh];
__device__ __align__(16) __nv_bfloat16 g_Blo[Ll * Hh * Hh];
__device__ __align__(16) __nv_bfloat16 g_Xhi[(size_t)Mpad * FIN];
__device__ __align__(16) __nv_bfloat16 g_Xlo[(size_t)Mpad * FIN];
__device__ __align__(16) __nv_bfloat16 g_PBhi[FIN * Hh];
__device__ __align__(16) __nv_bfloat16 g_PBlo[FIN * Hh];

// ---------------- asm helpers ----------------
__device__ __forceinline__ uint32_t smem_u32(const void* p) {
    uint32_t a;
    asm("{ .reg .u64 t; cvta.to.shared.u64 t, %1; cvt.u32.u64 %0, t; }" : "=r"(a) : "l"(p));
    return a;
}
#define CPA(dst, src) \
    asm volatile("cp.async.cg.shared.global [%0], [%1], 16;" :: "r"(dst), "l"(src) : "memory")
#define LDSM4(r, addr) \
    asm volatile("ldmatrix.sync.aligned.m8n8.x4.shared.b16 {%0,%1,%2,%3}, [%4];" \
        : "=r"((r)[0]), "=r"((r)[1]), "=r"((r)[2]), "=r"((r)[3]) : "r"(addr))
#define LDSM4T(r, addr) \
    asm volatile("ldmatrix.sync.aligned.m8n8.x4.trans.shared.b16 {%0,%1,%2,%3}, [%4];" \
        : "=r"((r)[0]), "=r"((r)[1]), "=r"((r)[2]), "=r"((r)[3]) : "r"(addr))
#define MMA16816(c, a, b) \
    asm volatile("mma.sync.aligned.m16n8k16.row.col.f32.bf16.bf16.f32 " \
        "{%0,%1,%2,%3}, {%4,%5,%6,%7}, {%8,%9}, {%0,%1,%2,%3};" \
        : "+f"((c)[0]), "+f"((c)[1]), "+f"((c)[2]), "+f"((c)[3]) \
        : "r"((a)[0]), "r"((a)[1]), "r"((a)[2]), "r"((a)[3]), "r"((b)[0]), "r"((b)[1]))

__device__ __forceinline__ uint32_t pack_hi2(float x, float y) {
    __nv_bfloat16 a = __float2bfloat16(x), b = __float2bfloat16(y);
    return ((uint32_t)*(uint16_t*)&b << 16) | *(uint16_t*)&a;
}
__device__ __forceinline__ uint32_t pack_lo2(float x, float y) {
    __nv_bfloat16 a = __float2bfloat16(x), b = __float2bfloat16(y);
    __nv_bfloat16 la = __float2bfloat16(x - __bfloat162float(a));
    __nv_bfloat16 lb = __float2bfloat16(y - __bfloat162float(b));
    return ((uint32_t)*(uint16_t*)&lb << 16) | *(uint16_t*)&la;
}
// reconstruct 2 floats from packed bf16 hi + lo words
__device__ __forceinline__ float2 unpack2(uint32_t hi, uint32_t lo) {
    __nv_bfloat162 h = *(__nv_bfloat162*)&hi;
    __nv_bfloat162 l = *(__nv_bfloat162*)&lo;
    float2 r;
    r.x = __bfloat162float(h.x) + __bfloat162float(l.x);
    r.y = __bfloat162float(h.y) + __bfloat162float(l.y);
    return r;
}
// 4 fp16 (uint2) -> 4 fp32 fma into acc
__device__ __forceinline__ void fma4(float4& acc, uint2 q, float w) {
    float2 a = __half22float2(*(__half2*)&q.x);
    float2 b = __half22float2(*(__half2*)&q.y);
    acc.x = fmaf(a.x, w, acc.x);
    acc.y = fmaf(a.y, w, acc.y);
    acc.z = fmaf(b.x, w, acc.z);
    acc.w = fmaf(b.y, w, acc.w);
}

// ---------------- setup kernels ----------------
// split x -> bf16 hi/lo AND zero g_cnt (fused; grid covers Nn*FIN/4 > Nn)
__global__ void k_split_x(const float* __restrict__ x) {
    int idx = blockIdx.x * blockDim.x + threadIdx.x;
    if (idx < Nn) g_cnt[idx] = 0;
    if (idx >= Nn * FIN / 4) return;
    float4 v = *(const float4*)&x[idx * 4];
    uint2 hv, lv;
    hv.x = pack_hi2(v.x, v.y); hv.y = pack_hi2(v.z, v.w);
    lv.x = pack_lo2(v.x, v.y); lv.y = pack_lo2(v.z, v.w);
    *(uint2*)&g_Xhi[idx * 4] = hv;
    *(uint2*)&g_Xlo[idx * 4] = lv;
}
__global__ void k_wsplit(const float* __restrict__ convW, const float* __restrict__ projW) {
    int idx = blockIdx.x * blockDim.x + threadIdx.x;
    if (idx < Ll * Hh * Hh) {
        float w = convW[idx];
        __nv_bfloat16 hi = __float2bfloat16(w);
        g_Bhi[idx] = hi;
        g_Blo[idx] = __float2bfloat16(w - __bfloat162float(hi));
    } else if (idx < Ll * Hh * Hh + FIN * Hh) {
        int j = idx - Ll * Hh * Hh;
        float w = projW[j];
        __nv_bfloat16 hi = __float2bfloat16(w);
        g_PBhi[j] = hi;
        g_PBlo[j] = __float2bfloat16(w - __bfloat162float(hi));
    }
}
__global__ void k_count_edges(const int* __restrict__ ei) {
    int e = blockIdx.x * blockDim.x + threadIdx.x;
    if (e < Ee) atomicAdd(&g_cnt[ei[Ee + e]], 1);
}
__global__ void k_scan_block() {
    __shared__ int s[1024];
    int gid = blockIdx.x * 1024 + threadIdx.x;
    int v = (gid < Nn) ? g_cnt[gid] : 0;
    s[threadIdx.x] = v;
    for (int d = 1; d < 1024; d <<= 1) {
        __syncthreads();
        int t = (threadIdx.x >= d) ? s[threadIdx.x - d] : 0;
        __syncthreads();
        s[threadIdx.x] += t;
    }
    __syncthreads();
    if (gid < Nn) g_off[gid] = s[threadIdx.x] - v;
    if (threadIdx.x == 1023) g_part[blockIdx.x] = s[1023];
}
__global__ void k_scan_add() {
    __shared__ int base;
    if (threadIdx.x == 0) {
        int acc = 0;
        for (int i = 0; i < blockIdx.x; i++) acc += g_part[i];
        base = acc;
    }
    __syncthreads();
    int gid = blockIdx.x * 1024 + threadIdx.x;
    if (gid < Nn) {
        int v = g_off[gid] + base;
        g_off[gid] = v;
        g_cur[gid] = v;
        g_isd[gid] = rsqrtf(1.0f + (float)g_cnt[gid]);
    }
    if (gid == 0) g_off[Nn] = Ee;
}
__global__ void k_csr_fill(const int* __restrict__ ei) {
    int e = blockIdx.x * blockDim.x + threadIdx.x;
    if (e < Ee) {
        int s = ei[e];
        int d = ei[Ee + e];
        int p = atomicAdd(&g_cur[d], 1);
        g_csr[p] = s;
        g_wgt[p] = g_isd[s] * g_isd[d];
    }
}

// ---------------- bf16x3 mma.sync GEMM, 4-slot K16 cp.async ring ----------------
// MODE 0 (conv): A = g_Ahi/g_Alo [Mpad,256], B = g_Bhi/g_Blo + layer, C = g_hWh (fp16)
// MODE 1 (proj): A = g_Xhi/g_Xlo [Mpad,64],  B = g_PBhi/g_PBlo, C = relu(.+bias) -> hi/lo split
#define SLOT   20992
#define ALO_O  6144
#define BHI_O  12288
#define BLO_O  16640
#define SMEM_G (4 * SLOT)   // 83968

template<int KSTAGES, int MODE>
__global__ __launch_bounds__(256, 2) void k_gemm_mma(int layer, const float* __restrict__ bias) {
    extern __shared__ __align__(16) unsigned char smraw[];
    const int tid = threadIdx.x, lane = tid & 31, wid = tid >> 5;
    const int warp_m = wid & 3, warp_n = wid >> 2;
    const int m0 = blockIdx.x * 128, n0 = blockIdx.y * 128;
    const uint32_t sb = smem_u32(smraw);
    const int kdim = KSTAGES * 16;

    const __nv_bfloat16* Ah = (MODE == 0) ? g_Ahi : g_Xhi;
    const __nv_bfloat16* Al = (MODE == 0) ? g_Alo : g_Xlo;
    const __nv_bfloat16* Bh = (MODE == 0) ? g_Bhi + (size_t)layer * Hh * Hh : g_PBhi;
    const __nv_bfloat16* Bl = (MODE == 0) ? g_Blo + (size_t)layer * Hh * Hh : g_PBlo;

    const int a_r = tid >> 1, a_c = tid & 1;
    const int b_r = tid >> 4, b_c = tid & 15;

#define LOAD_STAGE(slotbase, kt) do { \
        int k0 = (kt) * 16; \
        CPA((slotbase) + a_r * 48 + a_c * 16, \
            Ah + (size_t)(m0 + a_r) * kdim + k0 + a_c * 8); \
        CPA((slotbase) + ALO_O + a_r * 48 + a_c * 16, \
            Al + (size_t)(m0 + a_r) * kdim + k0 + a_c * 8); \
        CPA((slotbase) + BHI_O + b_r * 272 + b_c * 16, \
            Bh + (size_t)(k0 + b_r) * Hh + n0 + b_c * 8); \
        CPA((slotbase) + BLO_O + b_r * 272 + b_c * 16, \
            Bl + (size_t)(k0 + b_r) * Hh + n0 + b_c * 8); \
        asm volatile("cp.async.commit_group;" ::: "memory"); \
    } while (0)

    float acc[2][8][4];
    #pragma unroll
    for (int i = 0; i < 2; i++)
        #pragma unroll
        for (int j = 0; j < 8; j++)
            #pragma unroll
            for (int q = 0; q < 4; q++) acc[i][j][q] = 0.f;

    const uint32_t aoff = sb + (warp_m * 32 + (lane & 15)) * 48 + (lane >> 4) * 16;
    const uint32_t boff = sb + BHI_O + (lane & 15) * 272 + (warp_n * 8 + (lane >> 4)) * 16;

    LOAD_STAGE(sb, 0);
    LOAD_STAGE(sb + SLOT, 1);
    LOAD_STAGE(sb + 2 * SLOT, 2);

    #pragma unroll
    for (int kt = 0; kt < KSTAGES; kt++) {
        const uint32_t s = (kt & 3) * SLOT;
        asm volatile("cp.async.wait_group 2;" ::: "memory");
        __syncthreads();
        if (kt + 3 < KSTAGES) {
            LOAD_STAGE(sb + ((kt + 3) & 3) * SLOT, kt + 3);
        } else {
            asm volatile("cp.async.commit_group;" ::: "memory");
        }

        uint32_t ah[2][4], al[2][4], bh[4][4], bl[4][4];
        #pragma unroll
        for (int mt = 0; mt < 2; mt++) {
            LDSM4(ah[mt], aoff + s + mt * 768);
            LDSM4(al[mt], aoff + s + ALO_O + mt * 768);
        }
        #pragma unroll
        for (int nt = 0; nt < 4; nt++) {
            LDSM4T(bh[nt], boff + s + nt * 32);
            LDSM4T(bl[nt], boff + s + (BLO_O - BHI_O) + nt * 32);
        }
        #pragma unroll
        for (int mt = 0; mt < 2; mt++)
            #pragma unroll
            for (int nt = 0; nt < 4; nt++)
                #pragma unroll
                for (int nb = 0; nb < 2; nb++) {
                    float* c = acc[mt][nt * 2 + nb];
                    MMA16816(c, ah[mt], &bh[nt][nb * 2]);
                    MMA16816(c, ah[mt], &bl[nt][nb * 2]);
                    MMA16816(c, al[mt], &bh[nt][nb * 2]);
                }
    }
#undef LOAD_STAGE

    #pragma unroll
    for (int mt = 0; mt < 2; mt++) {
        int rbase = m0 + warp_m * 32 + mt * 16 + (lane >> 2);
        #pragma unroll
        for (int half = 0; half < 2; half++) {
            int r = rbase + half * 8;
            #pragma unroll
            for (int j = 0; j < 8; j++) {
                int n = n0 + warp_n * 64 + j * 8 + (lane & 3) * 2;
                float vx = acc[mt][j][half * 2 + 0];
                float vy = acc[mt][j][half * 2 + 1];
                if (MODE == 0) {
                    __half2 hv = __floats2half2_rn(vx, vy);
                    *(__half2*)&g_hWh[(size_t)r * Hh + n] = hv;
                } else if (r < Nn) {
                    float2 bi = *(const float2*)&bias[n];
                    vx = fmaxf(vx + bi.x, 0.f);
                    vy = fmaxf(vy + bi.y, 0.f);
                    *(uint32_t*)&g_Ahi[(size_t)r * Hh + n] = pack_hi2(vx, vy);
                    *(uint32_t*)&g_Alo[(size_t)r * Hh + n] = pack_lo2(vx, vy);
                }
            }
        }
    }
}

// ---------------- SIMT SGEMM (head only) ----------------
__global__ void k_sgemm(const float* __restrict__ B, const float* __restrict__ bias,
                        int M, int N, int K, int sel) {
    const float* A = (sel == 2) ? g_pool : g_f1;
    float*       C = (sel == 2) ? g_f1  : g_f2;

    __shared__ float As[16][64];
    __shared__ float Bs[16][68];

    int tid = threadIdx.x;
    int m0 = blockIdx.y * 64, n0 = blockIdx.x * 64;
    int tr = tid >> 4, tc = tid & 15;
    int arow = tid >> 2, aq = (tid & 3) * 4;
    int brow = tid >> 4, bq = (tid & 15) * 4;

    float acc[4][4];
    #pragma unroll
    for (int i = 0; i < 4; i++)
        #pragma unroll
        for (int j = 0; j < 4; j++) acc[i][j] = 0.f;

    for (int k0 = 0; k0 < K; k0 += 16) {
        float4 av;
        if (m0 + arow < M)
            av = *reinterpret_cast<const float4*>(&A[(size_t)(m0 + arow) * K + k0 + aq]);
        else
            av = make_float4(0.f, 0.f, 0.f, 0.f);
        As[aq + 0][arow] = av.x;
        As[aq + 1][arow] = av.y;
        As[aq + 2][arow] = av.z;
        As[aq + 3][arow] = av.w;

        float4 bv = *reinterpret_cast<const float4*>(&B[(size_t)(k0 + brow) * N + n0 + bq]);
        Bs[brow][bq + 0] = bv.x;
        Bs[brow][bq + 1] = bv.y;
        Bs[brow][bq + 2] = bv.z;
        Bs[brow][bq + 3] = bv.w;
        __syncthreads();

        #pragma unroll
        for (int k = 0; k < 16; k++) {
            float arr[4], br[4];
            #pragma unroll
            for (int i = 0; i < 4; i++) arr[i] = As[k][tr * 4 + i];
            #pragma unroll
            for (int j = 0; j < 4; j++) br[j] = Bs[k][tc * 4 + j];
            #pragma unroll
            for (int i = 0; i < 4; i++)
                #pragma unroll
                for (int j = 0; j < 4; j++) acc[i][j] = fmaf(arr[i], br[j], acc[i][j]);
        }
        __syncthreads();
    }

    #pragma unroll
    for (int i = 0; i < 4; i++) {
        int m = m0 + tr * 4 + i;
        if (m >= M) continue;
        #pragma unroll
        for (int j = 0; j < 4; j++) {
            int n = n0 + tc * 4 + j;
            float v = fmaxf(acc[i][j] + bias[n], 0.f);
            C[(size_t)m * N + n] = v;
        }
    }
}

// ---------------- fused aggregation (round-9 champion loop) + hi/lo residual ----------------
__global__ __launch_bounds__(256) void k_agg_fused(
        const float* __restrict__ bias, const float* __restrict__ gamma,
        const float* __restrict__ beta, const float* __restrict__ mean,
        const float* __restrict__ var) {
    int v = blockIdx.x * 4 + (threadIdx.x >> 6);
    if (v >= Nn) return;
    int c = (threadIdx.x & 63) * 4;   // 4 features per thread

    float idv = g_isd[v];
    float ws = idv * idv;

    float4 acc;
    {
        uint2 sr = *(const uint2*)&g_hWh[(size_t)v * Hh + c];
        float2 s0 = __half22float2(*(__half2*)&sr.x);
        float2 s1 = __half22float2(*(__half2*)&sr.y);
        acc = make_float4(s0.x * ws, s0.y * ws, s1.x * ws, s1.y * ws);
    }

    int j = g_off[v], e = g_off[v + 1];
    for (; j + 4 <= e; j += 4) {
        int u0 = g_csr[j], u1 = g_csr[j + 1], u2 = g_csr[j + 2], u3 = g_csr[j + 3];
        float w0 = g_wgt[j], w1 = g_wgt[j + 1], w2 = g_wgt[j + 2], w3 = g_wgt[j + 3];
        uint2 q0 = *(const uint2*)&g_hWh[(size_t)u0 * Hh + c];
        uint2 q1 = *(const uint2*)&g_hWh[(size_t)u1 * Hh + c];
        uint2 q2 = *(const uint2*)&g_hWh[(size_t)u2 * Hh + c];
        uint2 q3 = *(const uint2*)&g_hWh[(size_t)u3 * Hh + c];
        fma4(acc, q0, w0);
        fma4(acc, q1, w1);
        fma4(acc, q2, w2);
        fma4(acc, q3, w3);
    }
    for (; j < e; j++) {
        int u = g_csr[j];
        float w = g_wgt[j];
        uint2 q = *(const uint2*)&g_hWh[(size_t)u * Hh + c];
        fma4(acc, q, w);
    }

    float4 bi = *(const float4*)&bias[c];
    float4 ga = *(const float4*)&gamma[c];
    float4 be = *(const float4*)&beta[c];
    float4 me = *(const float4*)&mean[c];
    float4 va = *(const float4*)&var[c];

    // residual from bf16 hi/lo pair (h is stored only as the split)
    uint2 rh = *(const uint2*)&g_Ahi[(size_t)v * Hh + c];
    uint2 rl = *(const uint2*)&g_Alo[(size_t)v * Hh + c];
    float2 r01 = unpack2(rh.x, rl.x);
    float2 r23 = unpack2(rh.y, rl.y);

    float4 o;
    o.x = fmaxf((acc.x + bi.x - me.x) * (ga.x * rsqrtf(va.x + EPSc)) + be.x, 0.f) + r01.x;
    o.y = fmaxf((acc.y + bi.y - me.y) * (ga.y * rsqrtf(va.y + EPSc)) + be.y, 0.f) + r01.y;
    o.z = fmaxf((acc.z + bi.z - me.z) * (ga.z * rsqrtf(va.z + EPSc)) + be.z, 0.f) + r23.x;
    o.w = fmaxf((acc.w + bi.w - me.w) * (ga.w * rsqrtf(va.w + EPSc)) + be.w, 0.f) + r23.y;

    uint2 hv, lv;
    hv.x = pack_hi2(o.x, o.y); hv.y = pack_hi2(o.z, o.w);
    lv.x = pack_lo2(o.x, o.y); lv.y = pack_lo2(o.z, o.w);
    *(uint2*)&g_Ahi[(size_t)v * Hh + c] = hv;
    *(uint2*)&g_Alo[(size_t)v * Hh + c] = lv;
}

// ---------------- pooling (reads h = hi + lo) ----------------
__global__ void k_pool(const int* __restrict__ batch) {
    __shared__ int sbb[2];
    int grp = blockIdx.x, t = threadIdx.x;
    if (t < 2) {
        int key = grp + t;
        int lo = 0, hi = Nn;
        while (lo < hi) {
            int mid = (lo + hi) >> 1;
            if (batch[mid] < key) lo = mid + 1; else hi = mid;
        }
        sbb[t] = lo;
    }
    __syncthreads();
    int s = sbb[0], e = sbb[1];
    float sum = 0.f, mx = -FLT_MAX;
    for (int i = s; i < e; i++) {
        float v = __bfloat162float(g_Ahi[(size_t)i * Hh + t])
                + __bfloat162float(g_Alo[(size_t)i * Hh + t]);
        sum += v;
        mx = fmaxf(mx, v);
    }
    float c = (float)(e - s);
    g_pool[(size_t)grp * (2 * Hh) + t]      = sum / fmaxf(c, 1.f);
    g_pool[(size_t)grp * (2 * Hh) + Hh + t] = mx;
}

// ---------------- final tiny GEMM ----------------
__global__ void k_head3(const float* __restrict__ W, const float* __restrict__ b,
                        float* __restrict__ out) {
    int idx = blockIdx.x * blockDim.x + threadIdx.x;
    if (idx >= Gg * Tt) return;
    int r = idx >> 2, c = idx & 3;
    float acc = b[c];
    const float* row = &g_f2[(size_t)r * 128];
    #pragma unroll 8
    for (int k = 0; k < 128; k++) acc = fmaf(row[k], W[k * 4 + c], acc);
    out[idx] = acc;
}

// ---------------- launch ----------------
extern "C" void kernel_launch(void* const* d_in, const int* in_sizes, int n_in,
                              void* d_out, int out_size) {
    const float* x     = (const float*)d_in[0];
    const int*   ei    = (const int*)d_in[1];
    const int*   batch = (const int*)d_in[2];
    const float* projW = (const float*)d_in[3];
    const float* projb = (const float*)d_in[4];
    const float* convW = (const float*)d_in[5];
    const float* convb = (const float*)d_in[6];
    const float* gamma = (const float*)d_in[7];
    const float* beta  = (const float*)d_in[8];
    const float* mean  = (const float*)d_in[9];
    const float* var   = (const float*)d_in[10];
    const float* W1 = (const float*)d_in[11];
    const float* b1 = (const float*)d_in[12];
    const float* W2 = (const float*)d_in[13];
    const float* b2 = (const float*)d_in[14];
    const float* W3 = (const float*)d_in[15];
    const float* b3 = (const float*)d_in[16];
    float* out = (float*)d_out;

    const int SCAN_B = (Nn + 1023) / 1024;

    cudaFuncSetAttribute(k_gemm_mma<16, 0>, cudaFuncAttributeMaxDynamicSharedMemorySize, SMEM_G);
    cudaFuncSetAttribute(k_gemm_mma<4, 1>, cudaFuncAttributeMaxDynamicSharedMemorySize, SMEM_G);

    // splits (k_split_x also zeroes g_cnt)
    k_split_x  <<<(Nn * FIN / 4 + 255) / 256, 256>>>(x);
    k_wsplit   <<<(Ll * Hh * Hh + FIN * Hh + 255) / 256, 256>>>(convW, projW);

    // projection via mma path (epilogue -> hi/lo split only)
    k_gemm_mma<4, 1><<<dim3(MTILES, 2), 256, SMEM_G>>>(0, projb);

    // CSR build
    k_count_edges<<<(Ee + 255) / 256, 256>>>(ei);
    k_scan_block <<<SCAN_B, 1024>>>();
    k_scan_add   <<<SCAN_B, 1024>>>();
    k_csr_fill   <<<(Ee + 255) / 256, 256>>>(ei);

    // 4 GCN layers
    for (int l = 0; l < Ll; l++) {
        k_gemm_mma<16, 0><<<dim3(MTILES, 2), 256, SMEM_G>>>(l, nullptr);
        k_agg_fused<<<(Nn + 3) / 4, 256>>>(convb + l * Hh, gamma + l * Hh, beta + l * Hh,
                                           mean + l * Hh, var + l * Hh);
    }

    // pooling + head
    k_pool<<<Gg, 256>>>(batch);
    k_sgemm<<<dim3(Hh / 64, Gg / 64), 256>>>(W1, b1, Gg, Hh, 2 * Hh, 2);
    k_sgemm<<<dim3((Hh / 2) / 64, Gg / 64), 256>>>(W2, b2, Gg, Hh / 2, Hh, 3);
    k_head3<<<(Gg * Tt + 255) / 256, 256>>>(W3, b3, out);
}

// round 14
// speedup vs baseline: 1.1140x; 1.0031x over previous
#include <cuda_runtime.h>
#include <cuda_bf16.h>
#include <cuda_fp16.h>
#include <math.h>
#include <float.h>
#include <stdint.h>

#define Nn   50000
#define FIN  64
#define Hh   256
#define Ee   800000
#define Gg   2048
#define Ll   4
#define Tt   4
#define EPSc 1e-5f

#define MTILES ((Nn + 127) / 128)   // 391
#define Mpad   (MTILES * 128)       // 50048

// ---------------- scratch ----------------
__device__ __align__(16) __half g_hWh[(size_t)Mpad * Hh];   // fp16 message rows
__device__ float g_isd[Nn];
__device__ int   g_cnt[Nn];
__device__ int   g_off[Nn + 1];
__device__ int   g_cur[Nn];
__device__ int   g_csr[Ee];
__device__ float g_wgt[Ee];
__device__ int   g_part[64];
__device__ __align__(16) float g_pool[Gg * 2 * Hh];
__device__ __align__(16) float g_f1[Gg * Hh];
__device__ __align__(16) float g_f2[Gg * (Hh / 2)];
__device__ __align__(16) __nv_bfloat16 g_Ahi[(size_t)Mpad * Hh];
__device__ __align__(16) __nv_bfloat16 g_Alo[(size_t)Mpad * Hh];
__device__ __align__(16) __nv_bfloat16 g_Bhi[Ll * Hh * Hh];
__device__ __align__(16) __nv_bfloat16 g_Blo[Ll * Hh * Hh];
__device__ __align__(16) __nv_bfloat16 g_Xhi[(size_t)Mpad * FIN];
__device__ __align__(16) __nv_bfloat16 g_Xlo[(size_t)Mpad * FIN];
__device__ __align__(16) __nv_bfloat16 g_PBhi[FIN * Hh];
__device__ __align__(16) __nv_bfloat16 g_PBlo[FIN * Hh];

// ---------------- asm helpers ----------------
__device__ __forceinline__ uint32_t smem_u32(const void* p) {
    uint32_t a;
    asm("{ .reg .u64 t; cvta.to.shared.u64 t, %1; cvt.u32.u64 %0, t; }" : "=r"(a) : "l"(p));
    return a;
}
#define CPA(dst, src) \
    asm volatile("cp.async.cg.shared.global [%0], [%1], 16;" :: "r"(dst), "l"(src) : "memory")
#define LDSM4(r, addr) \
    asm volatile("ldmatrix.sync.aligned.m8n8.x4.shared.b16 {%0,%1,%2,%3}, [%4];" \
        : "=r"((r)[0]), "=r"((r)[1]), "=r"((r)[2]), "=r"((r)[3]) : "r"(addr))
#define LDSM4T(r, addr) \
    asm volatile("ldmatrix.sync.aligned.m8n8.x4.trans.shared.b16 {%0,%1,%2,%3}, [%4];" \
        : "=r"((r)[0]), "=r"((r)[1]), "=r"((r)[2]), "=r"((r)[3]) : "r"(addr))
#define MMA16816(c, a, b) \
    asm volatile("mma.sync.aligned.m16n8k16.row.col.f32.bf16.bf16.f32 " \
        "{%0,%1,%2,%3}, {%4,%5,%6,%7}, {%8,%9}, {%0,%1,%2,%3};" \
        : "+f"((c)[0]), "+f"((c)[1]), "+f"((c)[2]), "+f"((c)[3]) \
        : "r"((a)[0]), "r"((a)[1]), "r"((a)[2]), "r"((a)[3]), "r"((b)[0]), "r"((b)[1]))

__device__ __forceinline__ uint32_t pack_hi2(float x, float y) {
    __nv_bfloat16 a = __float2bfloat16(x), b = __float2bfloat16(y);
    return ((uint32_t)*(uint16_t*)&b << 16) | *(uint16_t*)&a;
}
__device__ __forceinline__ uint32_t pack_lo2(float x, float y) {
    __nv_bfloat16 a = __float2bfloat16(x), b = __float2bfloat16(y);
    __nv_bfloat16 la = __float2bfloat16(x - __bfloat162float(a));
    __nv_bfloat16 lb = __float2bfloat16(y - __bfloat162float(b));
    return ((uint32_t)*(uint16_t*)&lb << 16) | *(uint16_t*)&la;
}
__device__ __forceinline__ float2 unpack2(uint32_t hi, uint32_t lo) {
    __nv_bfloat162 h = *(__nv_bfloat162*)&hi;
    __nv_bfloat162 l = *(__nv_bfloat162*)&lo;
    float2 r;
    r.x = __bfloat162float(h.x) + __bfloat162float(l.x);
    r.y = __bfloat162float(h.y) + __bfloat162float(l.y);
    return r;
}
__device__ __forceinline__ void fma4(float4& acc, uint2 q, float w) {
    float2 a = __half22float2(*(__half2*)&q.x);
    float2 b = __half22float2(*(__half2*)&q.y);
    acc.x = fmaf(a.x, w, acc.x);
    acc.y = fmaf(a.y, w, acc.y);
    acc.z = fmaf(b.x, w, acc.z);
    acc.w = fmaf(b.y, w, acc.w);
}

// ---------------- setup kernels ----------------
__global__ void k_split_x(const float* __restrict__ x) {
    int idx = blockIdx.x * blockDim.x + threadIdx.x;
    if (idx < Nn) g_cnt[idx] = 0;
    if (idx >= Nn * FIN / 4) return;
    float4 v = *(const float4*)&x[idx * 4];
    uint2 hv, lv;
    hv.x = pack_hi2(v.x, v.y); hv.y = pack_hi2(v.z, v.w);
    lv.x = pack_lo2(v.x, v.y); lv.y = pack_lo2(v.z, v.w);
    *(uint2*)&g_Xhi[idx * 4] = hv;
    *(uint2*)&g_Xlo[idx * 4] = lv;
}
__global__ void k_wsplit(const float* __restrict__ convW, const float* __restrict__ projW) {
    int idx = blockIdx.x * blockDim.x + threadIdx.x;
    if (idx < Ll * Hh * Hh) {
        float w = convW[idx];
        __nv_bfloat16 hi = __float2bfloat16(w);
        g_Bhi[idx] = hi;
        g_Blo[idx] = __float2bfloat16(w - __bfloat162float(hi));
    } else if (idx < Ll * Hh * Hh + FIN * Hh) {
        int j = idx - Ll * Hh * Hh;
        float w = projW[j];
        __nv_bfloat16 hi = __float2bfloat16(w);
        g_PBhi[j] = hi;
        g_PBlo[j] = __float2bfloat16(w - __bfloat162float(hi));
    }
}
// 4 edges per thread, int4 dst loads
__global__ void k_count_edges(const int* __restrict__ ei) {
    int i = blockIdx.x * blockDim.x + threadIdx.x;
    if (i >= Ee / 4) return;
    int4 d4 = *(const int4*)&ei[Ee + i * 4];
    atomicAdd(&g_cnt[d4.x], 1);
    atomicAdd(&g_cnt[d4.y], 1);
    atomicAdd(&g_cnt[d4.z], 1);
    atomicAdd(&g_cnt[d4.w], 1);
}
__global__ void k_scan_block() {
    __shared__ int s[1024];
    int gid = blockIdx.x * 1024 + threadIdx.x;
    int v = (gid < Nn) ? g_cnt[gid] : 0;
    s[threadIdx.x] = v;
    for (int d = 1; d < 1024; d <<= 1) {
        __syncthreads();
        int t = (threadIdx.x >= d) ? s[threadIdx.x - d] : 0;
        __syncthreads();
        s[threadIdx.x] += t;
    }
    __syncthreads();
    if (gid < Nn) g_off[gid] = s[threadIdx.x] - v;
    if (threadIdx.x == 1023) g_part[blockIdx.x] = s[1023];
}
__global__ void k_scan_add() {
    __shared__ int base;
    if (threadIdx.x == 0) {
        int acc = 0;
        for (int i = 0; i < blockIdx.x; i++) acc += g_part[i];
        base = acc;
    }
    __syncthreads();
    int gid = blockIdx.x * 1024 + threadIdx.x;
    if (gid < Nn) {
        int v = g_off[gid] + base;
        g_off[gid] = v;
        g_cur[gid] = v;
        g_isd[gid] = rsqrtf(1.0f + (float)g_cnt[gid]);
    }
    if (gid == 0) g_off[Nn] = Ee;
}
// 4 edges per thread, int4 src/dst loads
__global__ void k_csr_fill(const int* __restrict__ ei) {
    int i = blockIdx.x * blockDim.x + threadIdx.x;
    if (i >= Ee / 4) return;
    int4 s4 = *(const int4*)&ei[i * 4];
    int4 d4 = *(const int4*)&ei[Ee + i * 4];
    int p0 = atomicAdd(&g_cur[d4.x], 1);
    int p1 = atomicAdd(&g_cur[d4.y], 1);
    int p2 = atomicAdd(&g_cur[d4.z], 1);
    int p3 = atomicAdd(&g_cur[d4.w], 1);
    g_csr[p0] = s4.x; g_wgt[p0] = g_isd[s4.x] * g_isd[d4.x];
    g_csr[p1] = s4.y; g_wgt[p1] = g_isd[s4.y] * g_isd[d4.y];
    g_csr[p2] = s4.z; g_wgt[p2] = g_isd[s4.z] * g_isd[d4.z];
    g_csr[p3] = s4.w; g_wgt[p3] = g_isd[s4.w] * g_isd[d4.w];
}

// ---------------- bf16x3 mma.sync GEMM, 4-slot K16 cp.async ring ----------------
#define SLOT   20992
#define ALO_O  6144
#define BHI_O  12288
#define BLO_O  16640
#define SMEM_G (4 * SLOT)   // 83968

template<int KSTAGES, int MODE>
__global__ __launch_bounds__(256, 2) void k_gemm_mma(int layer, const float* __restrict__ bias) {
    extern __shared__ __align__(16) unsigned char smraw[];
    const int tid = threadIdx.x, lane = tid & 31, wid = tid >> 5;
    const int warp_m = wid & 3, warp_n = wid >> 2;
    const int m0 = blockIdx.x * 128, n0 = blockIdx.y * 128;
    const uint32_t sb = smem_u32(smraw);
    const int kdim = KSTAGES * 16;

    const __nv_bfloat16* Ah = (MODE == 0) ? g_Ahi : g_Xhi;
    const __nv_bfloat16* Al = (MODE == 0) ? g_Alo : g_Xlo;
    const __nv_bfloat16* Bh = (MODE == 0) ? g_Bhi + (size_t)layer * Hh * Hh : g_PBhi;
    const __nv_bfloat16* Bl = (MODE == 0) ? g_Blo + (size_t)layer * Hh * Hh : g_PBlo;

    const int a_r = tid >> 1, a_c = tid & 1;
    const int b_r = tid >> 4, b_c = tid & 15;

#define LOAD_STAGE(slotbase, kt) do { \
        int k0 = (kt) * 16; \
        CPA((slotbase) + a_r * 48 + a_c * 16, \
            Ah + (size_t)(m0 + a_r) * kdim + k0 + a_c * 8); \
        CPA((slotbase) + ALO_O + a_r * 48 + a_c * 16, \
            Al + (size_t)(m0 + a_r) * kdim + k0 + a_c * 8); \
        CPA((slotbase) + BHI_O + b_r * 272 + b_c * 16, \
            Bh + (size_t)(k0 + b_r) * Hh + n0 + b_c * 8); \
        CPA((slotbase) + BLO_O + b_r * 272 + b_c * 16, \
            Bl + (size_t)(k0 + b_r) * Hh + n0 + b_c * 8); \
        asm volatile("cp.async.commit_group;" ::: "memory"); \
    } while (0)

    float acc[2][8][4];
    #pragma unroll
    for (int i = 0; i < 2; i++)
        #pragma unroll
        for (int j = 0; j < 8; j++)
            #pragma unroll
            for (int q = 0; q < 4; q++) acc[i][j][q] = 0.f;

    const uint32_t aoff = sb + (warp_m * 32 + (lane & 15)) * 48 + (lane >> 4) * 16;
    const uint32_t boff = sb + BHI_O + (lane & 15) * 272 + (warp_n * 8 + (lane >> 4)) * 16;

    LOAD_STAGE(sb, 0);
    LOAD_STAGE(sb + SLOT, 1);
    LOAD_STAGE(sb + 2 * SLOT, 2);

    #pragma unroll
    for (int kt = 0; kt < KSTAGES; kt++) {
        const uint32_t s = (kt & 3) * SLOT;
        asm volatile("cp.async.wait_group 2;" ::: "memory");
        __syncthreads();
        if (kt + 3 < KSTAGES) {
            LOAD_STAGE(sb + ((kt + 3) & 3) * SLOT, kt + 3);
        } else {
            asm volatile("cp.async.commit_group;" ::: "memory");
        }

        uint32_t ah[2][4], al[2][4], bh[4][4], bl[4][4];
        #pragma unroll
        for (int mt = 0; mt < 2; mt++) {
            LDSM4(ah[mt], aoff + s + mt * 768);
            LDSM4(al[mt], aoff + s + ALO_O + mt * 768);
        }
        #pragma unroll
        for (int nt = 0; nt < 4; nt++) {
            LDSM4T(bh[nt], boff + s + nt * 32);
            LDSM4T(bl[nt], boff + s + (BLO_O - BHI_O) + nt * 32);
        }
        #pragma unroll
        for (int mt = 0; mt < 2; mt++)
            #pragma unroll
            for (int nt = 0; nt < 4; nt++)
                #pragma unroll
                for (int nb = 0; nb < 2; nb++) {
                    float* c = acc[mt][nt * 2 + nb];
                    MMA16816(c, ah[mt], &bh[nt][nb * 2]);
                    MMA16816(c, ah[mt], &bl[nt][nb * 2]);
                    MMA16816(c, al[mt], &bh[nt][nb * 2]);
                }
    }
#undef LOAD_STAGE

    #pragma unroll
    for (int mt = 0; mt < 2; mt++) {
        int rbase = m0 + warp_m * 32 + mt * 16 + (lane >> 2);
        #pragma unroll
        for (int half = 0; half < 2; half++) {
            int r = rbase + half * 8;
            #pragma unroll
            for (int j = 0; j < 8; j++) {
                int n = n0 + warp_n * 64 + j * 8 + (lane & 3) * 2;
                float vx = acc[mt][j][half * 2 + 0];
                float vy = acc[mt][j][half * 2 + 1];
                if (MODE == 0) {
                    __half2 hv = __floats2half2_rn(vx, vy);
                    *(__half2*)&g_hWh[(size_t)r * Hh + n] = hv;
                } else if (r < Nn) {
                    float2 bi = *(const float2*)&bias[n];
                    vx = fmaxf(vx + bi.x, 0.f);
                    vy = fmaxf(vy + bi.y, 0.f);
                    *(uint32_t*)&g_Ahi[(size_t)r * Hh + n] = pack_hi2(vx, vy);
                    *(uint32_t*)&g_Alo[(size_t)r * Hh + n] = pack_lo2(vx, vy);
                }
            }
        }
    }
}

// ---------------- SIMT SGEMM (head only) ----------------
__global__ void k_sgemm(const float* __restrict__ B, const float* __restrict__ bias,
                        int M, int N, int K, int sel) {
    const float* A = (sel == 2) ? g_pool : g_f1;
    float*       C = (sel == 2) ? g_f1  : g_f2;

    __shared__ float As[16][64];
    __shared__ float Bs[16][68];

    int tid = threadIdx.x;
    int m0 = blockIdx.y * 64, n0 = blockIdx.x * 64;
    int tr = tid >> 4, tc = tid & 15;
    int arow = tid >> 2, aq = (tid & 3) * 4;
    int brow = tid >> 4, bq = (tid & 15) * 4;

    float acc[4][4];
    #pragma unroll
    for (int i = 0; i < 4; i++)
        #pragma unroll
        for (int j = 0; j < 4; j++) acc[i][j] = 0.f;

    for (int k0 = 0; k0 < K; k0 += 16) {
        float4 av;
        if (m0 + arow < M)
            av = *reinterpret_cast<const float4*>(&A[(size_t)(m0 + arow) * K + k0 + aq]);
        else
            av = make_float4(0.f, 0.f, 0.f, 0.f);
        As[aq + 0][arow] = av.x;
        As[aq + 1][arow] = av.y;
        As[aq + 2][arow] = av.z;
        As[aq + 3][arow] = av.w;

        float4 bv = *reinterpret_cast<const float4*>(&B[(size_t)(k0 + brow) * N + n0 + bq]);
        Bs[brow][bq + 0] = bv.x;
        Bs[brow][bq + 1] = bv.y;
        Bs[brow][bq + 2] = bv.z;
        Bs[brow][bq + 3] = bv.w;
        __syncthreads();

        #pragma unroll
        for (int k = 0; k < 16; k++) {
            float arr[4], br[4];
            #pragma unroll
            for (int i = 0; i < 4; i++) arr[i] = As[k][tr * 4 + i];
            #pragma unroll
            for (int j = 0; j < 4; j++) br[j] = Bs[k][tc * 4 + j];
            #pragma unroll
            for (int i = 0; i < 4; i++)
                #pragma unroll
                for (int j = 0; j < 4; j++) acc[i][j] = fmaf(arr[i], br[j], acc[i][j]);
        }
        __syncthreads();
    }

    #pragma unroll
    for (int i = 0; i < 4; i++) {
        int m = m0 + tr * 4 + i;
        if (m >= M) continue;
        #pragma unroll
        for (int j = 0; j < 4; j++) {
            int n = n0 + tc * 4 + j;
            float v = fmaxf(acc[i][j] + bias[n], 0.f);
            C[(size_t)m * N + n] = v;
        }
    }
}

// ---------------- fused aggregation (champion loop) + hi/lo residual ----------------
__global__ __launch_bounds__(256) void k_agg_fused(
        const float* __restrict__ bias, const float* __restrict__ gamma,
        const float* __restrict__ beta, const float* __restrict__ mean,
        const float* __restrict__ var) {
    int v = blockIdx.x * 4 + (threadIdx.x >> 6);
    if (v >= Nn) return;
    int c = (threadIdx.x & 63) * 4;

    float idv = g_isd[v];
    float ws = idv * idv;

    float4 acc;
    {
        uint2 sr = *(const uint2*)&g_hWh[(size_t)v * Hh + c];
        float2 s0 = __half22float2(*(__half2*)&sr.x);
        float2 s1 = __half22float2(*(__half2*)&sr.y);
        acc = make_float4(s0.x * ws, s0.y * ws, s1.x * ws, s1.y * ws);
    }

    int j = g_off[v], e = g_off[v + 1];
    for (; j + 4 <= e; j += 4) {
        int u0 = g_csr[j], u1 = g_csr[j + 1], u2 = g_csr[j + 2], u3 = g_csr[j + 3];
        float w0 = g_wgt[j], w1 = g_wgt[j + 1], w2 = g_wgt[j + 2], w3 = g_wgt[j + 3];
        uint2 q0 = *(const uint2*)&g_hWh[(size_t)u0 * Hh + c];
        uint2 q1 = *(const uint2*)&g_hWh[(size_t)u1 * Hh + c];
        uint2 q2 = *(const uint2*)&g_hWh[(size_t)u2 * Hh + c];
        uint2 q3 = *(const uint2*)&g_hWh[(size_t)u3 * Hh + c];
        fma4(acc, q0, w0);
        fma4(acc, q1, w1);
        fma4(acc, q2, w2);
        fma4(acc, q3, w3);
    }
    for (; j < e; j++) {
        int u = g_csr[j];
        float w = g_wgt[j];
        uint2 q = *(const uint2*)&g_hWh[(size_t)u * Hh + c];
        fma4(acc, q, w);
    }

    float4 bi = *(const float4*)&bias[c];
    float4 ga = *(const float4*)&gamma[c];
    float4 be = *(const float4*)&beta[c];
    float4 me = *(const float4*)&mean[c];
    float4 va = *(const float4*)&var[c];

    uint2 rh = *(const uint2*)&g_Ahi[(size_t)v * Hh + c];
    uint2 rl = *(const uint2*)&g_Alo[(size_t)v * Hh + c];
    float2 r01 = unpack2(rh.x, rl.x);
    float2 r23 = unpack2(rh.y, rl.y);

    float4 o;
    o.x = fmaxf((acc.x + bi.x - me.x) * (ga.x * rsqrtf(va.x + EPSc)) + be.x, 0.f) + r01.x;
    o.y = fmaxf((acc.y + bi.y - me.y) * (ga.y * rsqrtf(va.y + EPSc)) + be.y, 0.f) + r01.y;
    o.z = fmaxf((acc.z + bi.z - me.z) * (ga.z * rsqrtf(va.z + EPSc)) + be.z, 0.f) + r23.x;
    o.w = fmaxf((acc.w + bi.w - me.w) * (ga.w * rsqrtf(va.w + EPSc)) + be.w, 0.f) + r23.y;

    uint2 hv, lv;
    hv.x = pack_hi2(o.x, o.y); hv.y = pack_hi2(o.z, o.w);
    lv.x = pack_lo2(o.x, o.y); lv.y = pack_lo2(o.z, o.w);
    *(uint2*)&g_Ahi[(size_t)v * Hh + c] = hv;
    *(uint2*)&g_Alo[(size_t)v * Hh + c] = lv;
}

// ---------------- pooling: 2 graphs/block, 2 features/thread, packed loads ----------------
__global__ void k_pool(const int* __restrict__ batch) {
    __shared__ int sbb[3];
    int grp_base = blockIdx.x * 2;
    int sub = threadIdx.x >> 7;            // 0..1: which graph
    int t2 = (threadIdx.x & 127) * 2;      // feature pair
    if (threadIdx.x < 3) {
        int key = grp_base + threadIdx.x;
        int lo = 0, hi = Nn;
        while (lo < hi) {
            int mid = (lo + hi) >> 1;
            if (batch[mid] < key) lo = mid + 1; else hi = mid;
        }
        sbb[threadIdx.x] = lo;
    }
    __syncthreads();
    int grp = grp_base + sub;
    int s = sbb[sub], e = sbb[sub + 1];
    float2 sum = {0.f, 0.f}, mx = {-FLT_MAX, -FLT_MAX};
    for (int i = s; i < e; i++) {
        uint32_t hi = *(const uint32_t*)&g_Ahi[(size_t)i * Hh + t2];
        uint32_t lo = *(const uint32_t*)&g_Alo[(size_t)i * Hh + t2];
        float2 v = unpack2(hi, lo);
        sum.x += v.x; sum.y += v.y;
        mx.x = fmaxf(mx.x, v.x); mx.y = fmaxf(mx.y, v.y);
    }
    float cinv = 1.f / fmaxf((float)(e - s), 1.f);
    float* dst = &g_pool[(size_t)grp * (2 * Hh)];
    dst[t2]     = sum.x * cinv;
    dst[t2 + 1] = sum.y * cinv;
    dst[Hh + t2]     = mx.x;
    dst[Hh + t2 + 1] = mx.y;
}

// ---------------- final tiny GEMM ----------------
__global__ void k_head3(const float* __restrict__ W, const float* __restrict__ b,
                        float* __restrict__ out) {
    int idx = blockIdx.x * blockDim.x + threadIdx.x;
    if (idx >= Gg * Tt) return;
    int r = idx >> 2, c = idx & 3;
    float acc = b[c];
    const float* row = &g_f2[(size_t)r * 128];
    #pragma unroll 8
    for (int k = 0; k < 128; k++) acc = fmaf(row[k], W[k * 4 + c], acc);
    out[idx] = acc;
}

// ---------------- launch ----------------
extern "C" void kernel_launch(void* const* d_in, const int* in_sizes, int n_in,
                              void* d_out, int out_size) {
    const float* x     = (const float*)d_in[0];
    const int*   ei    = (const int*)d_in[1];
    const int*   batch = (const int*)d_in[2];
    const float* projW = (const float*)d_in[3];
    const float* projb = (const float*)d_in[4];
    const float* convW = (const float*)d_in[5];
    const float* convb = (const float*)d_in[6];
    const float* gamma = (const float*)d_in[7];
    const float* beta  = (const float*)d_in[8];
    const float* mean  = (const float*)d_in[9];
    const float* var   = (const float*)d_in[10];
    const float* W1 = (const float*)d_in[11];
    const float* b1 = (const float*)d_in[12];
    const float* W2 = (const float*)d_in[13];
    const float* b2 = (const float*)d_in[14];
    const float* W3 = (const float*)d_in[15];
    const float* b3 = (const float*)d_in[16];
    float* out = (float*)d_out;

    const int SCAN_B = (Nn + 1023) / 1024;

    cudaFuncSetAttribute(k_gemm_mma<16, 0>, cudaFuncAttributeMaxDynamicSharedMemorySize, SMEM_G);
    cudaFuncSetAttribute(k_gemm_mma<4, 1>, cudaFuncAttributeMaxDynamicSharedMemorySize, SMEM_G);

    // 0-2: splits + proj
    k_split_x  <<<(Nn * FIN / 4 + 255) / 256, 256>>>(x);
    k_wsplit   <<<(Ll * Hh * Hh + FIN * Hh + 255) / 256, 256>>>(convW, projW);
    k_gemm_mma<4, 1><<<dim3(MTILES, 2), 256, SMEM_G>>>(0, projb);

    // 3: conv GEMM layer 0 (depends only on proj) — lands in ncu window
    k_gemm_mma<16, 0><<<dim3(MTILES, 2), 256, SMEM_G>>>(0, nullptr);

    // CSR build (needed only before agg)
    k_count_edges<<<(Ee / 4 + 255) / 256, 256>>>(ei);
    k_scan_block <<<SCAN_B, 1024>>>();
    k_scan_add   <<<SCAN_B, 1024>>>();
    k_csr_fill   <<<(Ee / 4 + 255) / 256, 256>>>(ei);

    // layer 0 aggregation, then layers 1..3
    k_agg_fused<<<(Nn + 3) / 4, 256>>>(convb, gamma, beta, mean, var);
    for (int l = 1; l < Ll; l++) {
        k_gemm_mma<16, 0><<<dim3(MTILES, 2), 256, SMEM_G>>>(l, nullptr);
        k_agg_fused<<<(Nn + 3) / 4, 256>>>(convb + l * Hh, gamma + l * Hh, beta + l * Hh,
                                           mean + l * Hh, var + l * Hh);
    }

    // pooling + head
    k_pool<<<Gg / 2, 256>>>(batch);
    k_sgemm<<<dim3(Hh / 64, Gg / 64), 256>>>(W1, b1, Gg, Hh, 2 * Hh, 2);
    k_sgemm<<<dim3((Hh / 2) / 64, Gg / 64), 256>>>(W2, b2, Gg, Hh / 2, Hh, 3);
    k_head3<<<(Gg * Tt + 255) / 256, 256>>>(W3, b3, out);
}